// round 9
// baseline (speedup 1.0000x reference)
#include <cuda_runtime.h>
#include <cstdint>

#define NN 50000
#define NE 600000
#define NG 64

// ---------------- scratch (no allocations allowed) ----------------
__device__ __align__(16) float g_h  [(size_t)NN * 128];
__device__ __align__(16) float g_wt[4][128 * 128];   // tf32-rounded weights
__device__ __align__(16) float g_pool[NG * 128];
__device__ __align__(16) float g_cnt[NG];
__device__ int   g_is64;
// CSR scratch
__device__ __align__(16) int g_cntE[NN];
__device__ int    g_rowptr[NN + 1];
__device__ int    g_wofs[NN];
__device__ float4 g_erec[NE];      // {src(bitcast), a0, a1, a2} per dst-sorted slot
__device__ int    g_bsum[128];
__device__ int    g_barrier;

// ---------------- helpers ----------------
__device__ __forceinline__ void red_add_v2(float* addr, float a, float b) {
    asm volatile("red.global.add.v2.f32 [%0], {%1,%2};"
                 :: "l"(addr), "f"(a), "f"(b) : "memory");
}
__device__ __forceinline__ long long load_idx(const void* p, long long i, int is64) {
    if (is64) return ((const long long*)p)[i];
    return (long long)((const int*)p)[i];
}
__device__ __forceinline__ uint32_t f2tf32(float x) {
    uint32_t r;
    asm("cvt.rna.tf32.f32 %0, %1;" : "=r"(r) : "f"(x));
    return r;
}
__device__ __forceinline__ float f2tf32f(float x) { return __uint_as_float(f2tf32(x)); }
__device__ __forceinline__ uint32_t smem_u32(const void* p) {
    uint32_t a;
    asm("{ .reg .u64 t; cvta.to.shared.u64 t, %1; cvt.u32.u64 %0, t; }" : "=r"(a) : "l"(p));
    return a;
}
__device__ __forceinline__ void cpa16(uint32_t dst, const void* src, uint32_t sz) {
    asm volatile("cp.async.ca.shared.global [%0], [%1], 16, %2;"
                 :: "r"(dst), "l"(src), "r"(sz) : "memory");
}
#define CPA_COMMIT() asm volatile("cp.async.commit_group;" ::: "memory")
#define CPA_WAIT0()  asm volatile("cp.async.wait_group 0;" ::: "memory")

__device__ __forceinline__ void mma16n8k8(float* c, const uint32_t* a, uint32_t b0, uint32_t b1) {
    asm volatile("mma.sync.aligned.m16n8k8.row.col.f32.tf32.tf32.f32 "
                 "{%0,%1,%2,%3}, {%4,%5,%6,%7}, {%8,%9}, {%0,%1,%2,%3};"
                 : "+f"(c[0]), "+f"(c[1]), "+f"(c[2]), "+f"(c[3])
                 : "r"(a[0]), "r"(a[1]), "r"(a[2]), "r"(a[3]), "r"(b0), "r"(b1));
}

// ---------------- prelude: detect + zero + weight prep in ONE launch ----------------
__global__ void prelude_kernel(const int* __restrict__ ei32,
                               const float* __restrict__ w1a, const float* __restrict__ w1b,
                               const float* __restrict__ w2a, const float* __restrict__ w2b) {
    int b = blockIdx.x, tid = threadIdx.x;
    if (b == 0) {
        if (tid < 32) {
            int v = ei32[2 * tid + 1] | ei32[2 * (tid + 32) + 1];
            unsigned bl = __ballot_sync(0xffffffffu, v != 0);
            if (tid == 0) g_is64 = (bl == 0) ? 1 : 0;
        } else if (tid >= 64 && tid < 128) {
            g_cnt[tid - 64] = 0.f;
        } else if (tid == 128) {
            g_barrier = 0;
        }
        return;
    }
    if (b < 50) {
        int i = (b - 1) * 256 + tid;
        if (i < 12500) ((float4*)g_cntE)[i] = make_float4(0.f, 0.f, 0.f, 0.f);
        return;
    }
    if (b < 58) {
        int i = (b - 50) * 256 + tid;
        ((float4*)g_pool)[i] = make_float4(0.f, 0.f, 0.f, 0.f);
        return;
    }
    const float* src;
    float* dst;
    int i;
    if (b < 66)      { src = w1a; dst = g_wt[0]; i = (b - 58) * 256 + tid; }
    else if (b < 82) { src = w1b; dst = g_wt[1]; i = (b - 66) * 256 + tid; }
    else if (b < 98) { src = w2a; dst = g_wt[2]; i = (b - 82) * 256 + tid; }
    else             { src = w2b; dst = g_wt[3]; i = (b - 98) * 256 + tid; }
    float4 v = ((const float4*)src)[i];
    v.x = f2tf32f(v.x); v.y = f2tf32f(v.y); v.z = f2tf32f(v.z); v.w = f2tf32f(v.w);
    ((float4*)dst)[i] = v;
}

// ---------------- CSR build ----------------
__global__ void hist_kernel(const void* __restrict__ ei, int* __restrict__ cnt) {
    long long e = (long long)blockIdx.x * blockDim.x + threadIdx.x;
    if (e < NE) {
        long long dst = load_idx(ei, NE + e, g_is64);
        atomicAdd(&cnt[dst], 1);
    }
}

// single-kernel scan: local scan + global aggregate barrier + predecessor sum.
// 98 blocks, all co-resident -> spin barrier is deadlock-free.
__global__ void scanall_kernel(const int* __restrict__ cnt, int* __restrict__ rowptr,
                               int* __restrict__ wofs, const void* __restrict__ batch,
                               float* __restrict__ gcnt, int* __restrict__ bsum,
                               int* __restrict__ barrier) {
    __shared__ int wsum[16];
    __shared__ int bpre_s;
    int tid = threadIdx.x, lane = tid & 31, wid = tid >> 5;
    int b = blockIdx.x;
    int i = b * 512 + tid;
    int v = (i < NN) ? cnt[i] : 0;
    int s = v;
#pragma unroll
    for (int ofs = 1; ofs < 32; ofs <<= 1) {
        int t = __shfl_up_sync(0xffffffffu, s, ofs);
        if (lane >= ofs) s += t;
    }
    if (lane == 31) wsum[wid] = s;
    __syncthreads();
    if (wid == 0 && lane < 16) {
        int w = wsum[lane];
        int ws = w;
#pragma unroll
        for (int ofs = 1; ofs < 16; ofs <<= 1) {
            int t = __shfl_up_sync(0xffffu, ws, ofs);
            if (lane >= ofs) ws += t;
        }
        wsum[lane] = ws - w;
    }
    __syncthreads();
    int incl = s + wsum[wid];
    // publish block aggregate, arrive, wait for all
    if (tid == 511) {
        bsum[b] = incl;
        __threadfence();
        atomicAdd(barrier, 1);
    }
    if (tid == 0) {
        while (atomicAdd(barrier, 0) < (int)gridDim.x) {}
    }
    __syncthreads();
    // sum predecessor aggregates
    if (wid == 0) {
        int sum = 0;
        for (int j = lane; j < b; j += 32) sum += __ldcg(&bsum[j]);
#pragma unroll
        for (int o = 16; o; o >>= 1) sum += __shfl_down_sync(0xffffffffu, sum, o);
        if (lane == 0) bpre_s = sum;
    }
    __syncthreads();
    int r = incl - v + bpre_s;
    if (i < NN) {
        rowptr[i] = r;
        wofs[i] = r;
        long long g = load_idx(batch, i, g_is64);
        atomicAdd(&gcnt[g], 1.0f);
    }
    if (b == 0 && tid == 0) rowptr[NN] = NE;
}

__global__ void scatter_kernel(const void* __restrict__ ei, const float* __restrict__ attr,
                               int* __restrict__ wofs, float4* __restrict__ rec) {
    long long e = (long long)blockIdx.x * blockDim.x + threadIdx.x;
    if (e < NE) {
        int is64 = g_is64;
        long long dst = load_idx(ei, NE + e, is64);
        int src = (int)load_idx(ei, e, is64);
        int pos = atomicAdd(&wofs[dst], 1);
        float4 r;
        r.x = __int_as_float(src);
        r.y = __ldg(&attr[e * 3 + 0]);
        r.z = __ldg(&attr[e * 3 + 1]);
        r.w = __ldg(&attr[e * 3 + 2]);
        rec[pos] = r;
    }
}

// ---------------- fused layer: gather-agg (SMEM) + 2x tf32 GEMM ----------------
// Atile[128][132] doubles as Mid after GEMM1. Ws[2][16][136] double-buffered.
// POOL=false: C rows; POOL=true: red.add into pool[batch[row]].
template <int CH, bool POOL>
__global__ __launch_bounds__(256, 2) void layer_kernel(
    const float* __restrict__ x, const float4* __restrict__ recs,
    const float* __restrict__ ew, const float* __restrict__ eb,
    const int* __restrict__ rowptr,
    const float* __restrict__ W1, const float* __restrict__ b1,
    const float* __restrict__ W2, const float* __restrict__ b2,
    float* __restrict__ C, const void* __restrict__ batch) {
    extern __shared__ uint32_t sm[];
    uint32_t* Atile = sm;              // [128][132], becomes Mid
    uint32_t* Ws    = sm + 16896;      // [2][16][136]
    const uint32_t sm_b = smem_u32(sm);
    const uint32_t ws_b = sm_b + 16896u * 4u;

    const int tid = threadIdx.x, lane = tid & 31, wid = tid >> 5;
    const int block_row = blockIdx.x * 128;
    const int rbase = (wid & 3) * 32;
    const int cbase = (wid >> 2) * 64;
    const int g4 = lane >> 2;
    const int t4 = lane & 3;
    const int wr0 = tid >> 5, wcc = (tid & 31) * 4;
    const int wr1 = (tid + 256) >> 5;

    // prefetch W1 k-block 0 (overlaps gather phase)
    cpa16(ws_b + (wr0 * 136 + wcc) * 4, &W1[(long long)wr0 * 128 + wcc], 16);
    cpa16(ws_b + (wr1 * 136 + wcc) * 4, &W1[(long long)wr1 * 128 + wcc], 16);
    CPA_COMMIT();

    // ---- phase 0: gather-aggregate 128 rows into Atile (tf32) ----
    {
        const int VPL = CH / 32;
        const int c0 = lane * VPL;
        float ew0[VPL], ew1[VPL], ew2[VPL], ebv[VPL];
#pragma unroll
        for (int j = 0; j < VPL; j++) {
            ew0[j] = __ldg(&ew[c0 + j]);
            ew1[j] = __ldg(&ew[CH + c0 + j]);
            ew2[j] = __ldg(&ew[2 * CH + c0 + j]);
            ebv[j] = __ldg(&eb[c0 + j]);
        }
        for (int nn = 0; nn < 16; nn++) {
            int row = wid * 16 + nn;
            int node = block_row + row;
            if (node < NN) {
                float acc[VPL];
#pragma unroll
                for (int j = 0; j < VPL; j++) acc[j] = 0.f;
                int beg = __ldg(&rowptr[node]);
                int end = __ldg(&rowptr[node + 1]);
                int p = beg;
                for (; p + 3 < end; p += 4) {
                    float4 r[4];
                    float xv[4][VPL];
#pragma unroll
                    for (int u = 0; u < 4; u++) r[u] = __ldg(&recs[p + u]);
#pragma unroll
                    for (int u = 0; u < 4; u++) {
                        long long sidx = (long long)__float_as_int(r[u].x);
                        if (VPL == 4) *(float4*)xv[u] = *(const float4*)&x[sidx * CH + c0];
                        else          *(float2*)xv[u] = *(const float2*)&x[sidx * CH + c0];
                    }
#pragma unroll
                    for (int u = 0; u < 4; u++)
#pragma unroll
                        for (int j = 0; j < VPL; j++) {
                            float ev = ebv[j] + r[u].y * ew0[j] + r[u].z * ew1[j] + r[u].w * ew2[j];
                            acc[j] += fmaxf(xv[u][j] + ev, 0.f);
                        }
                }
                for (; p < end; p++) {
                    float4 r0 = __ldg(&recs[p]);
                    long long sidx = (long long)__float_as_int(r0.x);
                    float x0[VPL];
                    if (VPL == 4) *(float4*)x0 = *(const float4*)&x[sidx * CH + c0];
                    else          *(float2*)x0 = *(const float2*)&x[sidx * CH + c0];
#pragma unroll
                    for (int j = 0; j < VPL; j++) {
                        float e0 = ebv[j] + r0.y * ew0[j] + r0.z * ew1[j] + r0.w * ew2[j];
                        acc[j] += fmaxf(x0[j] + e0, 0.f);
                    }
                }
                float sv[VPL];
                if (VPL == 4) *(float4*)sv = *(const float4*)&x[(long long)node * CH + c0];
                else          *(float2*)sv = *(const float2*)&x[(long long)node * CH + c0];
#pragma unroll
                for (int j = 0; j < VPL; j++)
                    Atile[row * 132 + c0 + j] = f2tf32(sv[j] + acc[j]);
            } else {
#pragma unroll
                for (int j = 0; j < VPL; j++) Atile[row * 132 + c0 + j] = 0u;
            }
        }
    }
    __syncthreads();

    float acc[2][8][4];
#pragma unroll
    for (int i = 0; i < 2; i++)
#pragma unroll
        for (int j = 0; j < 8; j++)
#pragma unroll
            for (int q = 0; q < 4; q++) acc[i][j][q] = 0.f;

    // ---------- GEMM 1: acc = Atile @ W1 ----------
    const int NB1 = CH / 16;
    for (int kb = 0; kb < NB1; kb++) {
        CPA_WAIT0();
        __syncthreads();
        if (kb + 1 < NB1) {
            int k0 = (kb + 1) * 16;
            uint32_t wb = ws_b + ((kb + 1) & 1) * 2176 * 4;
            cpa16(wb + (wr0 * 136 + wcc) * 4, &W1[(long long)(k0 + wr0) * 128 + wcc], 16);
            cpa16(wb + (wr1 * 136 + wcc) * 4, &W1[(long long)(k0 + wr1) * 128 + wcc], 16);
            CPA_COMMIT();
        }
        const uint32_t* Wb = Ws + (kb & 1) * 2176;
        const int k0 = kb * 16;
#pragma unroll
        for (int ks = 0; ks < 2; ks++) {
            const int kk = k0 + ks * 8;
            uint32_t a[2][4];
#pragma unroll
            for (int i = 0; i < 2; i++) {
                int r = rbase + i * 16 + g4;
                a[i][0] = Atile[r * 132 + kk + t4];
                a[i][1] = Atile[(r + 8) * 132 + kk + t4];
                a[i][2] = Atile[r * 132 + kk + t4 + 4];
                a[i][3] = Atile[(r + 8) * 132 + kk + t4 + 4];
            }
#pragma unroll
            for (int j = 0; j < 8; j++) {
                int cn = cbase + j * 8 + g4;
                uint32_t b0 = Wb[(ks * 8 + t4) * 136 + cn];
                uint32_t b1 = Wb[(ks * 8 + t4 + 4) * 136 + cn];
#pragma unroll
                for (int i = 0; i < 2; i++) mma16n8k8(acc[i][j], a[i], b0, b1);
            }
        }
    }
    __syncthreads();
    // epilogue 1: Mid (=Atile) = tf32(relu(acc + b1))
#pragma unroll
    for (int j = 0; j < 8; j++) {
        int col = cbase + j * 8 + t4 * 2;
        float bx = __ldg(&b1[col]);
        float by = __ldg(&b1[col + 1]);
#pragma unroll
        for (int i = 0; i < 2; i++) {
            int r0 = rbase + i * 16 + g4;
            Atile[r0 * 132 + col]           = f2tf32(fmaxf(acc[i][j][0] + bx, 0.f));
            Atile[r0 * 132 + col + 1]       = f2tf32(fmaxf(acc[i][j][1] + by, 0.f));
            Atile[(r0 + 8) * 132 + col]     = f2tf32(fmaxf(acc[i][j][2] + bx, 0.f));
            Atile[(r0 + 8) * 132 + col + 1] = f2tf32(fmaxf(acc[i][j][3] + by, 0.f));
            acc[i][j][0] = 0.f; acc[i][j][1] = 0.f; acc[i][j][2] = 0.f; acc[i][j][3] = 0.f;
        }
    }
    __syncthreads();

    // ---------- GEMM 2: acc = Mid @ W2 ----------
    {
        cpa16(ws_b + (wr0 * 136 + wcc) * 4, &W2[(long long)wr0 * 128 + wcc], 16);
        cpa16(ws_b + (wr1 * 136 + wcc) * 4, &W2[(long long)wr1 * 128 + wcc], 16);
        CPA_COMMIT();
    }
    for (int kb = 0; kb < 8; kb++) {
        CPA_WAIT0();
        __syncthreads();
        if (kb + 1 < 8) {
            int k0 = (kb + 1) * 16;
            uint32_t wb = ws_b + ((kb + 1) & 1) * 2176 * 4;
            cpa16(wb + (wr0 * 136 + wcc) * 4, &W2[(long long)(k0 + wr0) * 128 + wcc], 16);
            cpa16(wb + (wr1 * 136 + wcc) * 4, &W2[(long long)(k0 + wr1) * 128 + wcc], 16);
            CPA_COMMIT();
        }
        const uint32_t* Wb = Ws + (kb & 1) * 2176;
        const int k0 = kb * 16;
#pragma unroll
        for (int ks = 0; ks < 2; ks++) {
            const int kk = k0 + ks * 8;
            uint32_t a[2][4];
#pragma unroll
            for (int i = 0; i < 2; i++) {
                int r = rbase + i * 16 + g4;
                a[i][0] = Atile[r * 132 + kk + t4];
                a[i][1] = Atile[(r + 8) * 132 + kk + t4];
                a[i][2] = Atile[r * 132 + kk + t4 + 4];
                a[i][3] = Atile[(r + 8) * 132 + kk + t4 + 4];
            }
#pragma unroll
            for (int j = 0; j < 8; j++) {
                int cn = cbase + j * 8 + g4;
                uint32_t b0 = Wb[(ks * 8 + t4) * 136 + cn];
                uint32_t b1 = Wb[(ks * 8 + t4 + 4) * 136 + cn];
#pragma unroll
                for (int i = 0; i < 2; i++) mma16n8k8(acc[i][j], a[i], b0, b1);
            }
        }
    }
    // epilogue 2
    if (POOL) {
        int is64 = g_is64;
        long long ga[2] = {0, 0}, gb[2] = {0, 0};
        bool va[2], vb[2];
#pragma unroll
        for (int i = 0; i < 2; i++) {
            int r0 = block_row + rbase + i * 16 + g4;
            va[i] = (r0 < NN);
            vb[i] = (r0 + 8 < NN);
            if (va[i]) ga[i] = load_idx(batch, r0, is64);
            if (vb[i]) gb[i] = load_idx(batch, r0 + 8, is64);
        }
#pragma unroll
        for (int j = 0; j < 8; j++) {
            int col = cbase + j * 8 + t4 * 2;
            float bx = __ldg(&b2[col]);
            float by = __ldg(&b2[col + 1]);
#pragma unroll
            for (int i = 0; i < 2; i++) {
                if (va[i])
                    red_add_v2(&C[ga[i] * 128 + col],
                               fmaxf(acc[i][j][0] + bx, 0.f), fmaxf(acc[i][j][1] + by, 0.f));
                if (vb[i])
                    red_add_v2(&C[gb[i] * 128 + col],
                               fmaxf(acc[i][j][2] + bx, 0.f), fmaxf(acc[i][j][3] + by, 0.f));
            }
        }
    } else {
#pragma unroll
        for (int j = 0; j < 8; j++) {
            int col = cbase + j * 8 + t4 * 2;
            float bx = __ldg(&b2[col]);
            float by = __ldg(&b2[col + 1]);
#pragma unroll
            for (int i = 0; i < 2; i++) {
                int r0 = block_row + rbase + i * 16 + g4;
                if (r0 < NN) {
                    float2 o0 = make_float2(fmaxf(acc[i][j][0] + bx, 0.f),
                                            fmaxf(acc[i][j][1] + by, 0.f));
                    *(float2*)&C[(long long)r0 * 128 + col] = o0;
                }
                if (r0 + 8 < NN) {
                    float2 o1 = make_float2(fmaxf(acc[i][j][2] + bx, 0.f),
                                            fmaxf(acc[i][j][3] + by, 0.f));
                    *(float2*)&C[(long long)(r0 + 8) * 128 + col] = o1;
                }
            }
        }
    }
}

// ---------------- finalize ----------------
__global__ void finalize_kernel(const float* __restrict__ pool, const float* __restrict__ cnt,
                                float* __restrict__ out) {
    int i = blockIdx.x * blockDim.x + threadIdx.x;
    if (i < NG * 128) out[i] = pool[i] / fmaxf(cnt[i >> 7], 1.0f);
}

// ---------------- launch ----------------
extern "C" void kernel_launch(void* const* d_in, const int* in_sizes, int n_in,
                              void* d_out, int out_size) {
    const float* x     = (const float*)d_in[0];
    const void*  ei    = d_in[1];
    const float* attr  = (const float*)d_in[2];
    const void*  batch = d_in[3];
    const float* el1_w = (const float*)d_in[4];
    const float* el1_b = (const float*)d_in[5];
    const float* w1a   = (const float*)d_in[6];
    const float* b1a   = (const float*)d_in[7];
    const float* w1b   = (const float*)d_in[8];
    const float* b1b   = (const float*)d_in[9];
    const float* el2_w = (const float*)d_in[10];
    const float* el2_b = (const float*)d_in[11];
    const float* w2a   = (const float*)d_in[12];
    const float* b2a   = (const float*)d_in[13];
    const float* w2b   = (const float*)d_in[14];
    const float* b2b   = (const float*)d_in[15];
    float* out = (float*)d_out;

    float *h, *pool, *cnt, *wt;
    int *cntE, *rowptr, *wofs, *bsum, *barrier;
    float4* erec;
    cudaGetSymbolAddress((void**)&h,    g_h);
    cudaGetSymbolAddress((void**)&pool, g_pool);
    cudaGetSymbolAddress((void**)&cnt,  g_cnt);
    cudaGetSymbolAddress((void**)&wt,   g_wt);
    cudaGetSymbolAddress((void**)&cntE,   g_cntE);
    cudaGetSymbolAddress((void**)&rowptr, g_rowptr);
    cudaGetSymbolAddress((void**)&wofs,   g_wofs);
    cudaGetSymbolAddress((void**)&erec,   g_erec);
    cudaGetSymbolAddress((void**)&bsum,   g_bsum);
    cudaGetSymbolAddress((void**)&barrier, g_barrier);
    float* wt1a = wt;
    float* wt1b = wt + 128 * 128;
    float* wt2a = wt + 2 * 128 * 128;
    float* wt2b = wt + 3 * 128 * 128;

    const int SMF = (128 * 132 + 2 * 16 * 136) * 4;   // 84992 B
    cudaFuncSetAttribute((const void*)layer_kernel<64, false>,
                         cudaFuncAttributeMaxDynamicSharedMemorySize, SMF);
    cudaFuncSetAttribute((const void*)layer_kernel<128, true>,
                         cudaFuncAttributeMaxDynamicSharedMemorySize, SMF);

    // 1: prelude
    prelude_kernel<<<114, 256>>>((const int*)ei, w1a, w1b, w2a, w2b);
    // 2-4: CSR build
    hist_kernel<<<(NE + 255) / 256, 256>>>(ei, cntE);
    scanall_kernel<<<(NN + 511) / 512, 512>>>(cntE, rowptr, wofs, batch, cnt, bsum, barrier);
    scatter_kernel<<<(NE + 255) / 256, 256>>>(ei, attr, wofs, erec);

    const int ggrid = (NN + 127) / 128;
    // 5: layer 1 (gather + MLP fused)
    layer_kernel<64, false><<<ggrid, 256, SMF>>>(x, erec, el1_w, el1_b, rowptr,
                                                 wt1a, b1a, wt1b, b1b, h, nullptr);
    // 6: layer 2 (gather + MLP + pool fused)
    layer_kernel<128, true><<<ggrid, 256, SMF>>>(h, erec, el2_w, el2_b, rowptr,
                                                 wt2a, b2a, wt2b, b2b, pool, batch);
    // 7: finalize
    finalize_kernel<<<(NG * 128 + 255) / 256, 256>>>(pool, cnt, out);
}

// round 10
// speedup vs baseline: 1.2316x; 1.2316x over previous
#include <cuda_runtime.h>
#include <cstdint>

#define NN 50000
#define NE 600000
#define NG 64

// ---------------- scratch (no allocations allowed) ----------------
__device__ __align__(16) float g_agg[(size_t)NN * 128];
__device__ __align__(16) float g_h  [(size_t)NN * 128];
__device__ __align__(16) float g_pool[NG * 128];
__device__ __align__(16) float g_cnt[NG];
__device__ int   g_is64;
// CSR scratch
__device__ __align__(16) int g_cntE[NN];
__device__ int    g_rowptr[NN + 1];
__device__ int    g_wofs[NN];
__device__ float4 g_erec[NE];      // {src(bitcast), a0, a1, a2} per dst-sorted slot
__device__ int    g_bsum[128];

// ---------------- helpers ----------------
__device__ __forceinline__ void red_add_v4(float* addr, float a, float b, float c, float d) {
    asm volatile("red.global.add.v4.f32 [%0], {%1,%2,%3,%4};"
                 :: "l"(addr), "f"(a), "f"(b), "f"(c), "f"(d) : "memory");
}
__device__ __forceinline__ long long load_idx(const void* p, long long i, int is64) {
    if (is64) return ((const long long*)p)[i];
    return (long long)((const int*)p)[i];
}
__device__ __forceinline__ uint32_t f2tf32(float x) {
    uint32_t r;
    asm("cvt.rna.tf32.f32 %0, %1;" : "=r"(r) : "f"(x));
    return r;
}
__device__ __forceinline__ void mma16n8k8(float* c, const uint32_t* a, uint32_t b0, uint32_t b1) {
    asm volatile("mma.sync.aligned.m16n8k8.row.col.f32.tf32.tf32.f32 "
                 "{%0,%1,%2,%3}, {%4,%5,%6,%7}, {%8,%9}, {%0,%1,%2,%3};"
                 : "+f"(c[0]), "+f"(c[1]), "+f"(c[2]), "+f"(c[3])
                 : "r"(a[0]), "r"(a[1]), "r"(a[2]), "r"(a[3]), "r"(b0), "r"(b1));
}

// ---------------- init: detect + ALL zeroing in one launch ----------------
// b0: detect is64 (warp0) + zero cnt (tid 64..127)
// b1..b50:  zero cntE   (12500 float4)
// b51..b58: zero pool   (2048 float4)
__global__ void init_kernel(const int* __restrict__ ei32) {
    int b = blockIdx.x, tid = threadIdx.x;
    if (b == 0) {
        if (tid < 32) {
            int v = ei32[2 * tid + 1] | ei32[2 * (tid + 32) + 1];
            unsigned bl = __ballot_sync(0xffffffffu, v != 0);
            if (tid == 0) g_is64 = (bl == 0) ? 1 : 0;
        } else if (tid >= 64 && tid < 128) {
            g_cnt[tid - 64] = 0.f;
        }
        return;
    }
    if (b <= 50) {
        int i = (b - 1) * 256 + tid;
        if (i < 12500) ((float4*)g_cntE)[i] = make_float4(0.f, 0.f, 0.f, 0.f);
        return;
    }
    int i = (b - 51) * 256 + tid;
    ((float4*)g_pool)[i] = make_float4(0.f, 0.f, 0.f, 0.f);
}

// ---------------- CSR build (dst-binned) ----------------
__global__ void hist_kernel(const void* __restrict__ ei, int* __restrict__ cnt) {
    long long e = (long long)blockIdx.x * blockDim.x + threadIdx.x;
    if (e < NE) {
        long long dst = load_idx(ei, NE + e, g_is64);
        atomicAdd(&cnt[dst], 1);
    }
}
__global__ void scan1_kernel(const int* __restrict__ cnt, int* __restrict__ rowptr,
                             int* __restrict__ bsum) {
    __shared__ int wsum[16];
    int tid = threadIdx.x, lane = tid & 31, wid = tid >> 5;
    int i = blockIdx.x * 512 + tid;
    int v = (i < NN) ? cnt[i] : 0;
    int s = v;
#pragma unroll
    for (int ofs = 1; ofs < 32; ofs <<= 1) {
        int t = __shfl_up_sync(0xffffffffu, s, ofs);
        if (lane >= ofs) s += t;
    }
    if (lane == 31) wsum[wid] = s;
    __syncthreads();
    if (wid == 0 && lane < 16) {
        int w = wsum[lane];
        int ws = w;
#pragma unroll
        for (int ofs = 1; ofs < 16; ofs <<= 1) {
            int t = __shfl_up_sync(0xffffu, ws, ofs);
            if (lane >= ofs) ws += t;
        }
        wsum[lane] = ws - w;
    }
    __syncthreads();
    int incl = s + wsum[wid];
    if (i < NN) rowptr[i] = incl - v;
    if (tid == 511) bsum[blockIdx.x] = incl;
}
__global__ void scan2_kernel(int* __restrict__ bsum, int nb) {
    __shared__ int s[128];
    int tid = threadIdx.x;
    int v = (tid < nb) ? bsum[tid] : 0;
    s[tid] = v;
    __syncthreads();
    for (int ofs = 1; ofs < 128; ofs <<= 1) {
        int t = (tid >= ofs) ? s[tid - ofs] : 0;
        __syncthreads();
        s[tid] += t;
        __syncthreads();
    }
    if (tid < nb) bsum[tid] = s[tid] - v;
}
__global__ void scan3_kernel(int* __restrict__ rowptr, const int* __restrict__ bsum,
                             int* __restrict__ wofs) {
    int i = blockIdx.x * blockDim.x + threadIdx.x;
    if (i < NN) {
        int r = rowptr[i] + bsum[i >> 9];
        rowptr[i] = r;
        wofs[i] = r;
    }
    if (i == 0) rowptr[NN] = NE;
}
__global__ void scatter_kernel(const void* __restrict__ ei, const float* __restrict__ attr,
                               int* __restrict__ wofs, float4* __restrict__ rec) {
    long long e = (long long)blockIdx.x * blockDim.x + threadIdx.x;
    if (e < NE) {
        int is64 = g_is64;
        long long dst = load_idx(ei, NE + e, is64);
        int src = (int)load_idx(ei, e, is64);
        int pos = atomicAdd(&wofs[dst], 1);
        float4 r;
        r.x = __int_as_float(src);
        r.y = __ldg(&attr[e * 3 + 0]);
        r.z = __ldg(&attr[e * 3 + 1]);
        r.w = __ldg(&attr[e * 3 + 2]);
        rec[pos] = r;
    }
}

// ---------------- gather aggregation: one warp per node (unroll 4) ----------------
// out[n] = x[n] + sum_{e: dst(e)=n} relu(x[src(e)] + attr(e) @ ew + eb)
template <int CH>
__global__ void agg_kernel(const float* __restrict__ x, const float4* __restrict__ recs,
                           const float* __restrict__ ew, const float* __restrict__ eb,
                           const int* __restrict__ rowptr, float* __restrict__ out) {
    const int VPL = CH / 32;
    int warp = (int)(((long long)blockIdx.x * blockDim.x + threadIdx.x) >> 5);
    int lane = threadIdx.x & 31;
    if (warp >= NN) return;
    int c0 = lane * VPL;
    float ew0[VPL], ew1[VPL], ew2[VPL], ebv[VPL], acc[VPL];
#pragma unroll
    for (int j = 0; j < VPL; j++) {
        ew0[j] = __ldg(&ew[c0 + j]);
        ew1[j] = __ldg(&ew[CH + c0 + j]);
        ew2[j] = __ldg(&ew[2 * CH + c0 + j]);
        ebv[j] = __ldg(&eb[c0 + j]);
        acc[j] = 0.f;
    }
    int beg = __ldg(&rowptr[warp]);
    int end = __ldg(&rowptr[warp + 1]);
    int p = beg;
    for (; p + 3 < end; p += 4) {
        float4 r[4];
        float xv[4][VPL];
#pragma unroll
        for (int u = 0; u < 4; u++) r[u] = __ldg(&recs[p + u]);
#pragma unroll
        for (int u = 0; u < 4; u++) {
            long long s = (long long)__float_as_int(r[u].x);
            if (VPL == 4) *(float4*)xv[u] = *(const float4*)&x[s * CH + c0];
            else          *(float2*)xv[u] = *(const float2*)&x[s * CH + c0];
        }
#pragma unroll
        for (int u = 0; u < 4; u++)
#pragma unroll
            for (int j = 0; j < VPL; j++) {
                float ev = ebv[j] + r[u].y * ew0[j] + r[u].z * ew1[j] + r[u].w * ew2[j];
                acc[j] += fmaxf(xv[u][j] + ev, 0.f);
            }
    }
    for (; p < end; p++) {
        float4 r0 = __ldg(&recs[p]);
        long long s0 = (long long)__float_as_int(r0.x);
        float x0[VPL];
        if (VPL == 4) *(float4*)x0 = *(const float4*)&x[s0 * CH + c0];
        else          *(float2*)x0 = *(const float2*)&x[s0 * CH + c0];
#pragma unroll
        for (int j = 0; j < VPL; j++) {
            float e0 = ebv[j] + r0.y * ew0[j] + r0.z * ew1[j] + r0.w * ew2[j];
            acc[j] += fmaxf(x0[j] + e0, 0.f);
        }
    }
    float sv[VPL];
    if (VPL == 4) *(float4*)sv = *(const float4*)&x[(long long)warp * CH + c0];
    else          *(float2*)sv = *(const float2*)&x[(long long)warp * CH + c0];
#pragma unroll
    for (int j = 0; j < VPL; j++) sv[j] += acc[j];
    if (VPL == 4) *(float4*)&out[(long long)warp * CH + c0] = *(float4*)sv;
    else          *(float2*)&out[(long long)warp * CH + c0] = *(float2*)sv;
}

// ---------------- fused 2-GEMM node MLP (tf32 mma.sync, inline cvt staging) ----------------
// C = relu( relu(A @ W1 + b1) @ W2 + b2 ), A:[N,K1], W1:[K1,128], W2:[128,128]
// Mid tile (128x128, tf32) lives in SMEM between the two GEMMs.
template <int K1>
__global__ __launch_bounds__(256, 2) void fused_mlp_kernel(
    const float* __restrict__ A, const float* __restrict__ W1, const float* __restrict__ b1,
    const float* __restrict__ W2, const float* __restrict__ b2, float* __restrict__ C) {
    extern __shared__ uint32_t sm[];
    uint32_t (*As)[20]   = (uint32_t(*)[20])sm;                    // 128x20
    uint32_t (*Ws)[136]  = (uint32_t(*)[136])(sm + 128 * 20);      // 16x136
    uint32_t (*Mid)[132] = (uint32_t(*)[132])(sm + 128 * 20 + 16 * 136);  // 128x132

    const int tid = threadIdx.x, lane = tid & 31, wid = tid >> 5;
    const int block_row = blockIdx.x * 128;
    const int rbase = (wid & 3) * 32;
    const int cbase = (wid >> 2) * 64;
    const int g4 = lane >> 2;
    const int t4 = lane & 3;

    float acc[2][8][4];
#pragma unroll
    for (int i = 0; i < 2; i++)
#pragma unroll
        for (int j = 0; j < 8; j++)
#pragma unroll
            for (int q = 0; q < 4; q++) acc[i][j][q] = 0.f;

    // ---------- GEMM 1: acc = A @ W1 ----------
    for (int k0 = 0; k0 < K1; k0 += 16) {
#pragma unroll
        for (int i = 0; i < 2; i++) {
            int idx = tid + i * 256;
            int r = idx >> 2;
            int kc = (idx & 3) * 4;
            int gr = block_row + r;
            float4 v = make_float4(0.f, 0.f, 0.f, 0.f);
            if (gr < NN) v = *(const float4*)&A[(long long)gr * K1 + k0 + kc];
            *(uint4*)&As[r][kc] = make_uint4(f2tf32(v.x), f2tf32(v.y), f2tf32(v.z), f2tf32(v.w));
        }
#pragma unroll
        for (int i = 0; i < 2; i++) {
            int idx = tid + i * 256;
            int r = idx >> 5;
            int cc = (idx & 31) * 4;
            float4 v = *(const float4*)&W1[(long long)(k0 + r) * 128 + cc];
            *(uint4*)&Ws[r][cc] = make_uint4(f2tf32(v.x), f2tf32(v.y), f2tf32(v.z), f2tf32(v.w));
        }
        __syncthreads();
#pragma unroll
        for (int ks = 0; ks < 2; ks++) {
            const int kk = ks * 8;
            uint32_t a[2][4];
#pragma unroll
            for (int i = 0; i < 2; i++) {
                int r = rbase + i * 16 + g4;
                a[i][0] = As[r][kk + t4];
                a[i][1] = As[r + 8][kk + t4];
                a[i][2] = As[r][kk + t4 + 4];
                a[i][3] = As[r + 8][kk + t4 + 4];
            }
#pragma unroll
            for (int j = 0; j < 8; j++) {
                int cn = cbase + j * 8 + g4;
                uint32_t b0 = Ws[kk + t4][cn];
                uint32_t b1 = Ws[kk + t4 + 4][cn];
#pragma unroll
                for (int i = 0; i < 2; i++) mma16n8k8(acc[i][j], a[i], b0, b1);
            }
        }
        __syncthreads();
    }
    // epilogue 1: Mid = tf32(relu(acc + b1)), stays in SMEM
#pragma unroll
    for (int j = 0; j < 8; j++) {
        int col = cbase + j * 8 + t4 * 2;
        float bx = __ldg(&b1[col]);
        float by = __ldg(&b1[col + 1]);
#pragma unroll
        for (int i = 0; i < 2; i++) {
            int r0 = rbase + i * 16 + g4;
            Mid[r0][col]         = f2tf32(fmaxf(acc[i][j][0] + bx, 0.f));
            Mid[r0][col + 1]     = f2tf32(fmaxf(acc[i][j][1] + by, 0.f));
            Mid[r0 + 8][col]     = f2tf32(fmaxf(acc[i][j][2] + bx, 0.f));
            Mid[r0 + 8][col + 1] = f2tf32(fmaxf(acc[i][j][3] + by, 0.f));
            acc[i][j][0] = 0.f; acc[i][j][1] = 0.f; acc[i][j][2] = 0.f; acc[i][j][3] = 0.f;
        }
    }
    __syncthreads();

    // ---------- GEMM 2: acc = Mid @ W2 (Mid from SMEM) ----------
    for (int k0 = 0; k0 < 128; k0 += 16) {
#pragma unroll
        for (int i = 0; i < 2; i++) {
            int idx = tid + i * 256;
            int r = idx >> 5;
            int cc = (idx & 31) * 4;
            float4 v = *(const float4*)&W2[(long long)(k0 + r) * 128 + cc];
            *(uint4*)&Ws[r][cc] = make_uint4(f2tf32(v.x), f2tf32(v.y), f2tf32(v.z), f2tf32(v.w));
        }
        __syncthreads();
#pragma unroll
        for (int ks = 0; ks < 2; ks++) {
            const int kk = ks * 8;
            uint32_t a[2][4];
#pragma unroll
            for (int i = 0; i < 2; i++) {
                int r = rbase + i * 16 + g4;
                a[i][0] = Mid[r][k0 + kk + t4];
                a[i][1] = Mid[r + 8][k0 + kk + t4];
                a[i][2] = Mid[r][k0 + kk + t4 + 4];
                a[i][3] = Mid[r + 8][k0 + kk + t4 + 4];
            }
#pragma unroll
            for (int j = 0; j < 8; j++) {
                int cn = cbase + j * 8 + g4;
                uint32_t b0 = Ws[kk + t4][cn];
                uint32_t b1 = Ws[kk + t4 + 4][cn];
#pragma unroll
                for (int i = 0; i < 2; i++) mma16n8k8(acc[i][j], a[i], b0, b1);
            }
        }
        __syncthreads();
    }
    // epilogue 2: C = relu(acc + b2)
#pragma unroll
    for (int j = 0; j < 8; j++) {
        int col = cbase + j * 8 + t4 * 2;
        float bx = __ldg(&b2[col]);
        float by = __ldg(&b2[col + 1]);
#pragma unroll
        for (int i = 0; i < 2; i++) {
            int r0 = block_row + rbase + i * 16 + g4;
            if (r0 < NN) {
                float2 o0 = make_float2(fmaxf(acc[i][j][0] + bx, 0.f),
                                        fmaxf(acc[i][j][1] + by, 0.f));
                *(float2*)&C[(long long)r0 * 128 + col] = o0;
            }
            if (r0 + 8 < NN) {
                float2 o1 = make_float2(fmaxf(acc[i][j][2] + bx, 0.f),
                                        fmaxf(acc[i][j][3] + by, 0.f));
                *(float2*)&C[(long long)(r0 + 8) * 128 + col] = o1;
            }
        }
    }
}

// ---------------- global mean pool ----------------
__global__ void pool_kernel(const float* __restrict__ h, const void* __restrict__ batch,
                            float* __restrict__ pool, float* __restrict__ cnt) {
    long long idx = (long long)blockIdx.x * blockDim.x + threadIdx.x;
    if (idx >= (long long)NN * 32) return;
    long long n = idx >> 5;
    int c4 = (int)(idx & 31) * 4;
    long long g = load_idx(batch, n, g_is64);
    float4 v = *(const float4*)&h[n * 128 + c4];
    red_add_v4(&pool[g * 128 + c4], v.x, v.y, v.z, v.w);
    if (c4 == 0) atomicAdd(&cnt[g], 1.0f);
}
__global__ void finalize_kernel(const float* __restrict__ pool, const float* __restrict__ cnt,
                                float* __restrict__ out) {
    int i = blockIdx.x * blockDim.x + threadIdx.x;
    if (i < NG * 128) out[i] = pool[i] / fmaxf(cnt[i >> 7], 1.0f);
}

// ---------------- launch ----------------
extern "C" void kernel_launch(void* const* d_in, const int* in_sizes, int n_in,
                              void* d_out, int out_size) {
    const float* x     = (const float*)d_in[0];
    const void*  ei    = d_in[1];
    const float* attr  = (const float*)d_in[2];
    const void*  batch = d_in[3];
    const float* el1_w = (const float*)d_in[4];
    const float* el1_b = (const float*)d_in[5];
    const float* w1a   = (const float*)d_in[6];
    const float* b1a   = (const float*)d_in[7];
    const float* w1b   = (const float*)d_in[8];
    const float* b1b   = (const float*)d_in[9];
    const float* el2_w = (const float*)d_in[10];
    const float* el2_b = (const float*)d_in[11];
    const float* w2a   = (const float*)d_in[12];
    const float* b2a   = (const float*)d_in[13];
    const float* w2b   = (const float*)d_in[14];
    const float* b2b   = (const float*)d_in[15];
    float* out = (float*)d_out;

    float *agg, *h, *pool, *cnt;
    int *cntE, *rowptr, *wofs, *bsum;
    float4* erec;
    cudaGetSymbolAddress((void**)&agg,  g_agg);
    cudaGetSymbolAddress((void**)&h,    g_h);
    cudaGetSymbolAddress((void**)&pool, g_pool);
    cudaGetSymbolAddress((void**)&cnt,  g_cnt);
    cudaGetSymbolAddress((void**)&cntE,   g_cntE);
    cudaGetSymbolAddress((void**)&rowptr, g_rowptr);
    cudaGetSymbolAddress((void**)&wofs,   g_wofs);
    cudaGetSymbolAddress((void**)&erec,   g_erec);
    cudaGetSymbolAddress((void**)&bsum,   g_bsum);

    const int SMF = (128 * 20 + 16 * 136 + 128 * 132) * 4;   // 86528 B
    cudaFuncSetAttribute(fused_mlp_kernel<64>,  cudaFuncAttributeMaxDynamicSharedMemorySize, SMF);
    cudaFuncSetAttribute(fused_mlp_kernel<128>, cudaFuncAttributeMaxDynamicSharedMemorySize, SMF);

    // 1: init (detect + all zeroing)
    init_kernel<<<59, 256>>>((const int*)ei);

    // 2-5: CSR build (once; reused by both layers)
    const int NB = (NN + 511) / 512;
    hist_kernel<<<(NE + 255) / 256, 256>>>(ei, cntE);
    scan1_kernel<<<NB, 512>>>(cntE, rowptr, bsum);
    scan2_kernel<<<1, 128>>>(bsum, NB);
    scan3_kernel<<<(NN + 255) / 256, 256>>>(rowptr, bsum, wofs);
    scatter_kernel<<<(NE + 255) / 256, 256>>>(ei, attr, wofs, erec);

    const int ggrid = (NN + 127) / 128;
    const int agrid = (int)(((long long)NN * 32 + 255) / 256);

    // layer 1
    agg_kernel<64><<<agrid, 256>>>(x, erec, el1_w, el1_b, rowptr, agg);
    fused_mlp_kernel<64><<<ggrid, 256, SMF>>>(agg, w1a, b1a, w1b, b1b, h);

    // layer 2
    agg_kernel<128><<<agrid, 256>>>(h, erec, el2_w, el2_b, rowptr, agg);
    fused_mlp_kernel<128><<<ggrid, 256, SMF>>>(agg, w2a, b2a, w2b, b2b, h);

    // pool + finalize
    {
        long long t = (long long)NN * 32;
        pool_kernel<<<(int)((t + 255) / 256), 256>>>(h, batch, pool, cnt);
    }
    finalize_kernel<<<(NG * 128 + 255) / 256, 256>>>(pool, cnt, out);
}